// round 14
// baseline (speedup 1.0000x reference)
#include <cuda_runtime.h>
#include <cuda_bf16.h>
#include <math.h>
#include <stdint.h>

#define Bn   2
#define Sn   4096
#define HIDn 1024
#define NHn  16
#define HDn  64
#define Wn   128
#define Mn   (Bn * Sn)          // 8192 rows
#define Kn   1024
#define NBLK (Sn / Wn)          // 32 query blocks
#define NEG_BIG (-3.402823466e38f)

// GEMM tile config: 128x128 CTA, 512 threads, 16 warps (4x4), 32x32 warp tile
#define BM 128
#define BN 128
#define KC 16
#define NCH (Kn / KC)            // 64 stages
#define RSB 48                   // padded row stride in BYTES
#define SEC_BYTES (128 * RSB)    // 6144
// bf16 3-term: 4 sections (Ah|Al|Wh|Wl)
#define STAGE_BYTES (4 * SEC_BYTES)   // 24576
#define SMEM_TOTAL (2 * STAGE_BYTES)  // 49152 static
// fp16 2-term: 3 sections (Ah|Al|W)
#define F_STAGE (3 * SEC_BYTES)       // 18432
#define F_SMEM (2 * F_STAGE)          // 36864 static

// ---------------- scratch: EXACTLY the proven 128MiB static set -------------
__device__ float g_q[Bn * NHn * Sn * HDn];
__device__ float g_k[Bn * NHn * Sn * HDn];
__device__ float g_v[Bn * NHn * Sn * HDn];
__device__ float g_ctx[Mn * HIDn];

// ---------------- macros ----------------------------------------------------
#define LDSM4(d0, d1, d2, d3, ad)                                              \
    asm volatile("ldmatrix.sync.aligned.m8n8.x4.shared.b16 {%0,%1,%2,%3}, [%4];" \
                 : "=r"(d0), "=r"(d1), "=r"(d2), "=r"(d3) : "r"(ad))

#define MMA_BF16(c0, c1, c2, c3, a0, a1, a2, a3, b0, b1)                       \
    asm volatile("mma.sync.aligned.m16n8k16.row.col.f32.bf16.bf16.f32 "        \
                 "{%0,%1,%2,%3}, {%4,%5,%6,%7}, {%8,%9}, {%0,%1,%2,%3};"        \
                 : "+f"(c0), "+f"(c1), "+f"(c2), "+f"(c3)                       \
                 : "r"(a0), "r"(a1), "r"(a2), "r"(a3), "r"(b0), "r"(b1))

#define MMA_F16(c0, c1, c2, c3, a0, a1, a2, a3, b0, b1)                        \
    asm volatile("mma.sync.aligned.m16n8k16.row.col.f32.f16.f16.f32 "          \
                 "{%0,%1,%2,%3}, {%4,%5,%6,%7}, {%8,%9}, {%0,%1,%2,%3};"        \
                 : "+f"(c0), "+f"(c1), "+f"(c2), "+f"(c3)                       \
                 : "r"(a0), "r"(a1), "r"(a2), "r"(a3), "r"(b0), "r"(b1))

#define CVT_SPLIT(v, h01, h23, l01, l23)                                       \
    do {                                                                       \
        asm("cvt.rn.bf16x2.f32 %0, %1, %2;" : "=r"(h01) : "f"((v).y), "f"((v).x)); \
        asm("cvt.rn.bf16x2.f32 %0, %1, %2;" : "=r"(h23) : "f"((v).w), "f"((v).z)); \
        float r0_ = (v).x - __uint_as_float((h01) << 16);                      \
        float r1_ = (v).y - __uint_as_float((h01) & 0xFFFF0000u);              \
        float r2_ = (v).z - __uint_as_float((h23) << 16);                      \
        float r3_ = (v).w - __uint_as_float((h23) & 0xFFFF0000u);              \
        asm("cvt.rn.bf16x2.f32 %0, %1, %2;" : "=r"(l01) : "f"(r1_), "f"(r0_)); \
        asm("cvt.rn.bf16x2.f32 %0, %1, %2;" : "=r"(l23) : "f"(r3_), "f"(r2_)); \
    } while (0)

#define SPLIT_STORE2(v, ah_, al_)                                              \
    do {                                                                       \
        uint32_t h01_, h23_, l01_, l23_;                                       \
        CVT_SPLIT(v, h01_, h23_, l01_, l23_);                                  \
        asm volatile("st.shared.v2.b32 [%0], {%1,%2};"                         \
                     :: "r"(ah_), "r"(h01_), "r"(h23_) : "memory");            \
        asm volatile("st.shared.v2.b32 [%0], {%1,%2};"                         \
                     :: "r"(al_), "r"(l01_), "r"(l23_) : "memory");            \
    } while (0)

#define CVT_SPLIT_F16(v, h01, h23, l01, l23)                                   \
    do {                                                                       \
        asm("cvt.rn.f16x2.f32 %0, %1, %2;" : "=r"(h01) : "f"((v).y), "f"((v).x)); \
        asm("cvt.rn.f16x2.f32 %0, %1, %2;" : "=r"(h23) : "f"((v).w), "f"((v).z)); \
        float b0_, b1_, b2_, b3_;                                              \
        asm("{.reg .f16 l_,h_; mov.b32 {l_,h_}, %2; cvt.f32.f16 %0, l_; "      \
            "cvt.f32.f16 %1, h_;}" : "=f"(b0_), "=f"(b1_) : "r"(h01));         \
        asm("{.reg .f16 l_,h_; mov.b32 {l_,h_}, %2; cvt.f32.f16 %0, l_; "      \
            "cvt.f32.f16 %1, h_;}" : "=f"(b2_), "=f"(b3_) : "r"(h23));         \
        float r0_ = (v).x - b0_, r1_ = (v).y - b1_;                            \
        float r2_ = (v).z - b2_, r3_ = (v).w - b3_;                            \
        asm("cvt.rn.f16x2.f32 %0, %1, %2;" : "=r"(l01) : "f"(r1_), "f"(r0_)); \
        asm("cvt.rn.f16x2.f32 %0, %1, %2;" : "=r"(l23) : "f"(r3_), "f"(r2_)); \
    } while (0)

#define SPLIT_STORE2_F16(v, ah_, al_)                                          \
    do {                                                                       \
        uint32_t h01_, h23_, l01_, l23_;                                       \
        CVT_SPLIT_F16(v, h01_, h23_, l01_, l23_);                              \
        asm volatile("st.shared.v2.b32 [%0], {%1,%2};"                         \
                     :: "r"(ah_), "r"(h01_), "r"(h23_) : "memory");            \
        asm volatile("st.shared.v2.b32 [%0], {%1,%2};"                         \
                     :: "r"(al_), "r"(l01_), "r"(l23_) : "memory");            \
    } while (0)

#define CVT_STORE_F16(v, aw_)                                                  \
    do {                                                                       \
        uint32_t h01_, h23_;                                                   \
        asm("cvt.rn.f16x2.f32 %0, %1, %2;" : "=r"(h01_) : "f"((v).y), "f"((v).x)); \
        asm("cvt.rn.f16x2.f32 %0, %1, %2;" : "=r"(h23_) : "f"((v).w), "f"((v).z)); \
        asm volatile("st.shared.v2.b32 [%0], {%1,%2};"                         \
                     :: "r"(aw_), "r"(h01_), "r"(h23_) : "memory");            \
    } while (0)

// ---------------- bf16 3-term GEMM (Q and K), 512 threads -------------------
__global__ void __launch_bounds__(512) gemm_mma(const float* __restrict__ A,
                                                const float* __restrict__ Wt,
                                                const float* __restrict__ bias,
                                                float* __restrict__ outp, int mode)
{
    __shared__ __align__(1024) char smem_buf[SMEM_TOTAL];
    const uint32_t smb = (uint32_t)__cvta_generic_to_shared(smem_buf);

    const int tid  = threadIdx.x;
    const int lane = tid & 31;
    const int wid  = tid >> 5;
    const int wm   = (wid >> 2) * 32;      // warp m offset (0/32/64/96)
    const int wn   = (wid & 3) * 32;       // warp n offset
    const int n0   = blockIdx.x * BN;
    const int m0   = blockIdx.y * BM;

    const float* Asrc = (mode == 3) ? g_ctx : A;

    // per-thread load slots: each thread loads ONE A float4 and ONE W float4
    const int r0 = tid >> 2;               // 0..127
    const int cq = tid & 3;
    const float* gpA = Asrc + (size_t)(m0 + r0) * Kn + cq * 4;
    const float* gpW = Wt   + (size_t)(n0 + r0) * Kn + cq * 4;
    const uint32_t soA = (uint32_t)(r0 * RSB + cq * 8);
    const uint32_t soW = 2u * SEC_BYTES + soA;

    float acc[2][4][4];
#pragma unroll
    for (int a = 0; a < 2; ++a)
#pragma unroll
        for (int b = 0; b < 4; ++b)
#pragma unroll
            for (int c = 0; c < 4; ++c) acc[a][b][c] = 0.f;

    float4 rvA = *(const float4*)gpA;
    float4 rvW = *(const float4*)gpW;
    SPLIT_STORE2(rvA, smb + soA, smb + soA + SEC_BYTES);
    SPLIT_STORE2(rvW, smb + soW, smb + soW + SEC_BYTES);

    const uint32_t a_roff = (uint32_t)(wm + (lane & 15)) * RSB
                          + (uint32_t)((lane >> 4) * 16);
    const uint32_t b_roff = 2u * SEC_BYTES
                          + (uint32_t)(wn + (lane & 7) + ((lane >> 4) << 3)) * RSB
                          + (uint32_t)(((lane >> 3) & 1) * 16);

    for (int ch = 0; ch < NCH; ++ch) {
        const uint32_t sb  = smb + (uint32_t)(ch & 1) * STAGE_BYTES;
        const uint32_t sb2 = smb + (uint32_t)((ch & 1) ^ 1) * STAGE_BYTES;
        __syncthreads();

        if (ch + 1 < NCH) {
            const int k0 = (ch + 1) * KC;
            rvA = *(const float4*)(gpA + k0);
            rvW = *(const float4*)(gpW + k0);
        }

        uint32_t ah[2][4], al[2][4];
#pragma unroll
        for (int mt = 0; mt < 2; ++mt) {
            uint32_t ad = sb + a_roff + (uint32_t)(mt * 16) * RSB;
            LDSM4(ah[mt][0], ah[mt][1], ah[mt][2], ah[mt][3], ad);
            LDSM4(al[mt][0], al[mt][1], al[mt][2], al[mt][3], ad + SEC_BYTES);
        }
#pragma unroll
        for (int p = 0; p < 2; ++p) {
            uint32_t bh[4], bl[4];
            uint32_t bd = sb + b_roff + (uint32_t)(p * 16) * RSB;
            LDSM4(bh[0], bh[1], bh[2], bh[3], bd);
            LDSM4(bl[0], bl[1], bl[2], bl[3], bd + SEC_BYTES);
#pragma unroll
            for (int mt = 0; mt < 2; ++mt) {
#pragma unroll
                for (int q = 0; q < 2; ++q) {
                    const int nt = p * 2 + q;
                    MMA_BF16(acc[mt][nt][0], acc[mt][nt][1],
                             acc[mt][nt][2], acc[mt][nt][3],
                             ah[mt][0], ah[mt][1], ah[mt][2], ah[mt][3],
                             bh[2*q], bh[2*q+1]);
                    MMA_BF16(acc[mt][nt][0], acc[mt][nt][1],
                             acc[mt][nt][2], acc[mt][nt][3],
                             al[mt][0], al[mt][1], al[mt][2], al[mt][3],
                             bh[2*q], bh[2*q+1]);
                    MMA_BF16(acc[mt][nt][0], acc[mt][nt][1],
                             acc[mt][nt][2], acc[mt][nt][3],
                             ah[mt][0], ah[mt][1], ah[mt][2], ah[mt][3],
                             bl[2*q], bl[2*q+1]);
                }
            }
        }

        if (ch + 1 < NCH) {
            SPLIT_STORE2(rvA, sb2 + soA, sb2 + soA + SEC_BYTES);
            SPLIT_STORE2(rvW, sb2 + soW, sb2 + soW + SEC_BYTES);
        }
    }

    float* qkv = (mode == 0) ? g_q : (mode == 1) ? g_k : g_v;
#pragma unroll
    for (int mt = 0; mt < 2; ++mt) {
#pragma unroll
        for (int nt = 0; nt < 4; ++nt) {
            const int gn = n0 + wn + nt * 8 + (lane & 3) * 2;
            const float b0 = bias[gn], b1 = bias[gn + 1];
#pragma unroll
            for (int h2 = 0; h2 < 2; ++h2) {
                const int gm = m0 + wm + mt * 16 + h2 * 8 + (lane >> 2);
                float2 v;
                v.x = acc[mt][nt][h2 * 2 + 0] + b0;
                v.y = acc[mt][nt][h2 * 2 + 1] + b1;
                if (mode <= 2) {
                    int bb = gm >> 12, ss = gm & 4095;
                    int hh = gn >> 6,  dd = gn & 63;
                    *(float2*)&qkv[((((size_t)bb * NHn + hh) * Sn) + ss) * HDn + dd] = v;
                } else {
                    *(float2*)&outp[(size_t)gm * HIDn + gn] = v;
                }
            }
        }
    }
}

// ---------------- fp16 2-term GEMM (V and O), 512 threads -------------------
__global__ void __launch_bounds__(512) gemm_f16(const float* __restrict__ A,
                                                const float* __restrict__ Wt,
                                                const float* __restrict__ bias,
                                                float* __restrict__ outp, int mode)
{
    __shared__ __align__(1024) char smem_buf[F_SMEM];
    const uint32_t smb = (uint32_t)__cvta_generic_to_shared(smem_buf);

    const int tid  = threadIdx.x;
    const int lane = tid & 31;
    const int wid  = tid >> 5;
    const int wm   = (wid >> 2) * 32;
    const int wn   = (wid & 3) * 32;
    const int n0   = blockIdx.x * BN;
    const int m0   = blockIdx.y * BM;

    const float* Asrc = (mode == 3) ? g_ctx : A;

    const int r0 = tid >> 2;
    const int cq = tid & 3;
    const float* gpA = Asrc + (size_t)(m0 + r0) * Kn + cq * 4;
    const float* gpW = Wt   + (size_t)(n0 + r0) * Kn + cq * 4;
    const uint32_t soA = (uint32_t)(r0 * RSB + cq * 8);
    const uint32_t soW = 2u * SEC_BYTES + soA;

    float acc[2][4][4];
#pragma unroll
    for (int a = 0; a < 2; ++a)
#pragma unroll
        for (int b = 0; b < 4; ++b)
#pragma unroll
            for (int c = 0; c < 4; ++c) acc[a][b][c] = 0.f;

    float4 rvA = *(const float4*)gpA;
    float4 rvW = *(const float4*)gpW;
    SPLIT_STORE2_F16(rvA, smb + soA, smb + soA + SEC_BYTES);
    CVT_STORE_F16(rvW, smb + soW);

    const uint32_t a_roff = (uint32_t)(wm + (lane & 15)) * RSB
                          + (uint32_t)((lane >> 4) * 16);
    const uint32_t b_roff = 2u * SEC_BYTES
                          + (uint32_t)(wn + (lane & 7) + ((lane >> 4) << 3)) * RSB
                          + (uint32_t)(((lane >> 3) & 1) * 16);

    for (int ch = 0; ch < NCH; ++ch) {
        const uint32_t sb  = smb + (uint32_t)(ch & 1) * F_STAGE;
        const uint32_t sb2 = smb + (uint32_t)((ch & 1) ^ 1) * F_STAGE;
        __syncthreads();

        if (ch + 1 < NCH) {
            const int k0 = (ch + 1) * KC;
            rvA = *(const float4*)(gpA + k0);
            rvW = *(const float4*)(gpW + k0);
        }

        uint32_t ah[2][4], al[2][4];
#pragma unroll
        for (int mt = 0; mt < 2; ++mt) {
            uint32_t ad = sb + a_roff + (uint32_t)(mt * 16) * RSB;
            LDSM4(ah[mt][0], ah[mt][1], ah[mt][2], ah[mt][3], ad);
            LDSM4(al[mt][0], al[mt][1], al[mt][2], al[mt][3], ad + SEC_BYTES);
        }
#pragma unroll
        for (int p = 0; p < 2; ++p) {
            uint32_t bh[4];
            uint32_t bd = sb + b_roff + (uint32_t)(p * 16) * RSB;
            LDSM4(bh[0], bh[1], bh[2], bh[3], bd);
#pragma unroll
            for (int mt = 0; mt < 2; ++mt) {
#pragma unroll
                for (int q = 0; q < 2; ++q) {
                    const int nt = p * 2 + q;
                    MMA_F16(acc[mt][nt][0], acc[mt][nt][1],
                            acc[mt][nt][2], acc[mt][nt][3],
                            ah[mt][0], ah[mt][1], ah[mt][2], ah[mt][3],
                            bh[2*q], bh[2*q+1]);
                    MMA_F16(acc[mt][nt][0], acc[mt][nt][1],
                            acc[mt][nt][2], acc[mt][nt][3],
                            al[mt][0], al[mt][1], al[mt][2], al[mt][3],
                            bh[2*q], bh[2*q+1]);
                }
            }
        }

        if (ch + 1 < NCH) {
            SPLIT_STORE2_F16(rvA, sb2 + soA, sb2 + soA + SEC_BYTES);
            CVT_STORE_F16(rvW, sb2 + soW);
        }
    }

#pragma unroll
    for (int mt = 0; mt < 2; ++mt) {
#pragma unroll
        for (int nt = 0; nt < 4; ++nt) {
            const int gn = n0 + wn + nt * 8 + (lane & 3) * 2;
            const float b0 = bias[gn], b1 = bias[gn + 1];
#pragma unroll
            for (int h2 = 0; h2 < 2; ++h2) {
                const int gm = m0 + wm + mt * 16 + h2 * 8 + (lane >> 2);
                float2 v;
                v.x = acc[mt][nt][h2 * 2 + 0] + b0;
                v.y = acc[mt][nt][h2 * 2 + 1] + b1;
                if (mode == 2) {
                    int bb = gm >> 12, ss = gm & 4095;
                    int hh = gn >> 6,  dd = gn & 63;
                    *(float2*)&g_v[((((size_t)bb * NHn + hh) * Sn) + ss) * HDn + dd] = v;
                } else {
                    *(float2*)&outp[(size_t)gm * HIDn + gn] = v;
                }
            }
        }
    }
}

// ---------------- RoPE (in place on g_q, g_k) ------------------------------
__global__ void rope_kernel()
{
    int t   = blockIdx.x * blockDim.x + threadIdx.x;
    int i   = t & 31;
    int row = t >> 5;
    int s   = row & (Sn - 1);

    double e = -(double)i * (9.210340371976184 / 32.0);
    float inv = (float)exp(e);
    float ang = (float)s * inv;
    float si, co;
    sincosf(ang, &si, &co);

    long base = (long)row * HDn;
    float x1 = g_q[base + i], x2 = g_q[base + i + 32];
    g_q[base + i]      = x1 * co - x2 * si;
    g_q[base + i + 32] = x2 * co + x1 * si;
    float y1 = g_k[base + i], y2 = g_k[base + i + 32];
    g_k[base + i]      = y1 * co - y2 * si;
    g_k[base + i + 32] = y2 * co + y1 * si;
}

// ---------------- banded attention -----------------------------------------
__global__ __launch_bounds__(128) void attn_kernel()
{
    __shared__ float smem_pool[8192];

    const int n  = blockIdx.x;
    const int h  = blockIdx.y;
    const int b  = blockIdx.z;
    const int qi = threadIdx.x;
    const int tid = threadIdx.x;

    const long headbase = ((long)(b * NHn + h)) * Sn;

    const float* qbase = g_q + (headbase + (long)n * Wn) * HDn;
    for (int i = tid; i < 2048; i += 128)
        ((float4*)smem_pool)[i] = ((const float4*)qbase)[i];
    __syncthreads();
    float rq[64];
#pragma unroll
    for (int d = 0; d < 64; ++d) rq[d] = smem_pool[qi * 64 + d];

    float m = NEG_BIG, l = 0.f;
    float acc[64];
#pragma unroll
    for (int d = 0; d < 64; ++d) acc[d] = 0.f;

    const int first_chunk = (n == 0) ? 2 : 0;

    for (int c = first_chunk; c < 4; ++c) {
        long krow0 = headbase + (long)((n - 1) * Wn + c * 64);
        const float* kb = g_k + krow0 * HDn;
        const float* vb = g_v + krow0 * HDn;
        __syncthreads();
        for (int i = tid; i < 1024; i += 128) {
            ((float4*)smem_pool)[i]        = ((const float4*)kb)[i];
            ((float4*)smem_pool)[1024 + i] = ((const float4*)vb)[i];
        }
        __syncthreads();

        for (int jt = 0; jt < 4; ++jt) {
            const int kj0 = c * 64 + jt * 16;
            float sc[16];
            float mx = NEG_BIG;
#pragma unroll
            for (int j = 0; j < 16; ++j) {
                int kj = kj0 + j;
                bool valid = (kj >= qi) && (kj <= qi + Wn);
                float s_ = NEG_BIG;
                if (valid) {
                    const float* kr = &smem_pool[(kj - c * 64) * 64];
                    float dot = 0.f;
#pragma unroll
                    for (int d = 0; d < 64; d += 4) {
                        float4 kv = *(const float4*)&kr[d];
                        dot += rq[d] * kv.x + rq[d+1] * kv.y
                             + rq[d+2] * kv.z + rq[d+3] * kv.w;
                    }
                    s_ = dot * 0.125f;
                }
                sc[j] = s_;
                mx = fmaxf(mx, s_);
            }
            float newm = fmaxf(m, mx);
            if (newm > NEG_BIG) {
                float f = __expf(m - newm);
                l *= f;
#pragma unroll
                for (int d = 0; d < 64; ++d) acc[d] *= f;
#pragma unroll
                for (int j = 0; j < 16; ++j) {
                    if (sc[j] > NEG_BIG) {
                        float p = __expf(sc[j] - newm);
                        l += p;
                        const float* vr = &smem_pool[4096 + (kj0 + j - c * 64) * 64];
#pragma unroll
                        for (int d = 0; d < 64; d += 4) {
                            float4 vv = *(const float4*)&vr[d];
                            acc[d]   += p * vv.x; acc[d+1] += p * vv.y;
                            acc[d+2] += p * vv.z; acc[d+3] += p * vv.w;
                        }
                    }
                }
                m = newm;
            }
        }
    }

    __syncthreads();
    float invl = 1.f / l;
#pragma unroll
    for (int d = 0; d < 64; ++d) smem_pool[qi * 64 + d] = acc[d] * invl;
    __syncthreads();

    float* obase = g_ctx + ((long)b * Sn + (long)n * Wn) * HIDn + h * HDn;
    for (int i = tid; i < 2048; i += 128) {
        int r  = i >> 4;
        int dq = i & 15;
        ((float4*)(obase + (long)r * HIDn))[dq] = ((const float4*)smem_pool)[i];
    }
}

// ---------------- launch ----------------------------------------------------
extern "C" void kernel_launch(void* const* d_in, const int* in_sizes, int n_in,
                              void* d_out, int out_size)
{
    const float* X  = (const float*)d_in[0];
    const float* Wq = (const float*)d_in[1];
    const float* bq = (const float*)d_in[2];
    const float* Wk = (const float*)d_in[3];
    const float* bk = (const float*)d_in[4];
    const float* Wv = (const float*)d_in[5];
    const float* bv = (const float*)d_in[6];
    const float* Wo = (const float*)d_in[7];
    const float* bo = (const float*)d_in[8];
    float* out = (float*)d_out;

    dim3 gg(HIDn / BN, Mn / BM);   // (8, 64)
    gemm_mma<<<gg, 512>>>(X, Wq, bq, nullptr, 0);   // Q: 3-term bf16
    gemm_mma<<<gg, 512>>>(X, Wk, bk, nullptr, 1);   // K: 3-term bf16
    gemm_f16<<<gg, 512>>>(X, Wv, bv, nullptr, 2);   // V: 2-term fp16

    rope_kernel<<<(Bn * NHn * Sn * 32) / 256, 256>>>();

    dim3 ag(NBLK, NHn, Bn);
    attn_kernel<<<ag, 128>>>();

    gemm_f16<<<gg, 512>>>(nullptr, Wo, bo, out, 3); // O: 2-term fp16
}

// round 15
// speedup vs baseline: 1.0575x; 1.0575x over previous
#include <cuda_runtime.h>
#include <cuda_bf16.h>
#include <math.h>
#include <stdint.h>

#define Bn   2
#define Sn   4096
#define HIDn 1024
#define NHn  16
#define HDn  64
#define Wn   128
#define Mn   (Bn * Sn)          // 8192 rows
#define Kn   1024
#define NBLK (Sn / Wn)          // 32 query blocks
#define NEG_BIG (-3.402823466e38f)

// GEMM tile config (R10-proven): 128x128 CTA, 64x32 warp tile, KC=16
#define BM 128
#define BN 128
#define KC 16
#define NCH (Kn / KC)            // 64 stages
#define RSB 48                   // padded row stride in BYTES
#define SEC_BYTES (128 * RSB)    // 6144
#define STAGE_BYTES (4 * SEC_BYTES)   // 24576 (bf16 3-term: Ah|Al|Wh|Wl)
#define SMEM_TOTAL (2 * STAGE_BYTES)  // 49152 static
#define F_STAGE (3 * SEC_BYTES)       // 18432 (fp16 2-term: Ah|Al|W)
#define F_SMEM (2 * F_STAGE)          // 36864 static

// ---------------- scratch: EXACTLY the proven 128MiB static set -------------
__device__ float g_q[Bn * NHn * Sn * HDn];
__device__ float g_k[Bn * NHn * Sn * HDn];
__device__ float g_v[Bn * NHn * Sn * HDn];
__device__ float g_ctx[Mn * HIDn];

// ---------------- macros ----------------------------------------------------
#define LDSM4(d0, d1, d2, d3, ad)                                              \
    asm volatile("ldmatrix.sync.aligned.m8n8.x4.shared.b16 {%0,%1,%2,%3}, [%4];" \
                 : "=r"(d0), "=r"(d1), "=r"(d2), "=r"(d3) : "r"(ad))

#define MMA_BF16(c0, c1, c2, c3, a0, a1, a2, a3, b0, b1)                       \
    asm volatile("mma.sync.aligned.m16n8k16.row.col.f32.bf16.bf16.f32 "        \
                 "{%0,%1,%2,%3}, {%4,%5,%6,%7}, {%8,%9}, {%0,%1,%2,%3};"        \
                 : "+f"(c0), "+f"(c1), "+f"(c2), "+f"(c3)                       \
                 : "r"(a0), "r"(a1), "r"(a2), "r"(a3), "r"(b0), "r"(b1))

#define MMA_F16(c0, c1, c2, c3, a0, a1, a2, a3, b0, b1)                        \
    asm volatile("mma.sync.aligned.m16n8k16.row.col.f32.f16.f16.f32 "          \
                 "{%0,%1,%2,%3}, {%4,%5,%6,%7}, {%8,%9}, {%0,%1,%2,%3};"        \
                 : "+f"(c0), "+f"(c1), "+f"(c2), "+f"(c3)                       \
                 : "r"(a0), "r"(a1), "r"(a2), "r"(a3), "r"(b0), "r"(b1))

#define CVT_SPLIT(v, h01, h23, l01, l23)                                       \
    do {                                                                       \
        asm("cvt.rn.bf16x2.f32 %0, %1, %2;" : "=r"(h01) : "f"((v).y), "f"((v).x)); \
        asm("cvt.rn.bf16x2.f32 %0, %1, %2;" : "=r"(h23) : "f"((v).w), "f"((v).z)); \
        float r0_ = (v).x - __uint_as_float((h01) << 16);                      \
        float r1_ = (v).y - __uint_as_float((h01) & 0xFFFF0000u);              \
        float r2_ = (v).z - __uint_as_float((h23) << 16);                      \
        float r3_ = (v).w - __uint_as_float((h23) & 0xFFFF0000u);              \
        asm("cvt.rn.bf16x2.f32 %0, %1, %2;" : "=r"(l01) : "f"(r1_), "f"(r0_)); \
        asm("cvt.rn.bf16x2.f32 %0, %1, %2;" : "=r"(l23) : "f"(r3_), "f"(r2_)); \
    } while (0)

#define SPLIT_STORE2(v, ah_, al_)                                              \
    do {                                                                       \
        uint32_t h01_, h23_, l01_, l23_;                                       \
        CVT_SPLIT(v, h01_, h23_, l01_, l23_);                                  \
        asm volatile("st.shared.v2.b32 [%0], {%1,%2};"                         \
                     :: "r"(ah_), "r"(h01_), "r"(h23_) : "memory");            \
        asm volatile("st.shared.v2.b32 [%0], {%1,%2};"                         \
                     :: "r"(al_), "r"(l01_), "r"(l23_) : "memory");            \
    } while (0)

#define CVT_SPLIT_F16(v, h01, h23, l01, l23)                                   \
    do {                                                                       \
        asm("cvt.rn.f16x2.f32 %0, %1, %2;" : "=r"(h01) : "f"((v).y), "f"((v).x)); \
        asm("cvt.rn.f16x2.f32 %0, %1, %2;" : "=r"(h23) : "f"((v).w), "f"((v).z)); \
        float b0_, b1_, b2_, b3_;                                              \
        asm("{.reg .f16 l_,h_; mov.b32 {l_,h_}, %2; cvt.f32.f16 %0, l_; "      \
            "cvt.f32.f16 %1, h_;}" : "=f"(b0_), "=f"(b1_) : "r"(h01));         \
        asm("{.reg .f16 l_,h_; mov.b32 {l_,h_}, %2; cvt.f32.f16 %0, l_; "      \
            "cvt.f32.f16 %1, h_;}" : "=f"(b2_), "=f"(b3_) : "r"(h23));         \
        float r0_ = (v).x - b0_, r1_ = (v).y - b1_;                            \
        float r2_ = (v).z - b2_, r3_ = (v).w - b3_;                            \
        asm("cvt.rn.f16x2.f32 %0, %1, %2;" : "=r"(l01) : "f"(r1_), "f"(r0_)); \
        asm("cvt.rn.f16x2.f32 %0, %1, %2;" : "=r"(l23) : "f"(r3_), "f"(r2_)); \
    } while (0)

#define SPLIT_STORE2_F16(v, ah_, al_)                                          \
    do {                                                                       \
        uint32_t h01_, h23_, l01_, l23_;                                       \
        CVT_SPLIT_F16(v, h01_, h23_, l01_, l23_);                              \
        asm volatile("st.shared.v2.b32 [%0], {%1,%2};"                         \
                     :: "r"(ah_), "r"(h01_), "r"(h23_) : "memory");            \
        asm volatile("st.shared.v2.b32 [%0], {%1,%2};"                         \
                     :: "r"(al_), "r"(l01_), "r"(l23_) : "memory");            \
    } while (0)

#define CVT_STORE_F16(v, aw_)                                                  \
    do {                                                                       \
        uint32_t h01_, h23_;                                                   \
        asm("cvt.rn.f16x2.f32 %0, %1, %2;" : "=r"(h01_) : "f"((v).y), "f"((v).x)); \
        asm("cvt.rn.f16x2.f32 %0, %1, %2;" : "=r"(h23_) : "f"((v).w), "f"((v).z)); \
        asm volatile("st.shared.v2.b32 [%0], {%1,%2};"                         \
                     :: "r"(aw_), "r"(h01_), "r"(h23_) : "memory");            \
    } while (0)

// ---------------- bf16 3-term GEMM (Q and K) --------------------------------
__global__ void __launch_bounds__(256) gemm_mma(const float* __restrict__ A,
                                                const float* __restrict__ Wt,
                                                const float* __restrict__ bias,
                                                float* __restrict__ outp, int mode)
{
    __shared__ __align__(1024) char smem_buf[SMEM_TOTAL];
    const uint32_t smb = (uint32_t)__cvta_generic_to_shared(smem_buf);

    const int tid  = threadIdx.x;
    const int lane = tid & 31;
    const int wid  = tid >> 5;
    const int wm   = (wid >> 2) * 64;
    const int wn   = (wid & 3) * 32;
    const int n0   = blockIdx.x * BN;
    const int m0   = blockIdx.y * BM;

    const float* Asrc = (mode == 3) ? g_ctx : A;

    const int r0 = tid >> 2;
    const int cq = tid & 3;
    const float* gp0 = Asrc + (size_t)(m0 + r0) * Kn + cq * 4;
    const float* gp1 = gp0 + (size_t)64 * Kn;
    const float* gp2 = Wt + (size_t)(n0 + r0) * Kn + cq * 4;
    const float* gp3 = gp2 + (size_t)64 * Kn;
    const uint32_t rcq = (uint32_t)(r0 * RSB + cq * 8);
    const uint32_t so0 = rcq;
    const uint32_t so1 = rcq + 64u * RSB;
    const uint32_t so2 = 2u * SEC_BYTES + rcq;
    const uint32_t so3 = 2u * SEC_BYTES + rcq + 64u * RSB;

    float acc[4][4][4];
#pragma unroll
    for (int a = 0; a < 4; ++a)
#pragma unroll
        for (int b = 0; b < 4; ++b)
#pragma unroll
            for (int c = 0; c < 4; ++c) acc[a][b][c] = 0.f;

    float4 rv0 = *(const float4*)gp0;
    float4 rv1 = *(const float4*)gp1;
    float4 rv2 = *(const float4*)gp2;
    float4 rv3 = *(const float4*)gp3;
    SPLIT_STORE2(rv0, smb + so0, smb + so0 + SEC_BYTES);
    SPLIT_STORE2(rv1, smb + so1, smb + so1 + SEC_BYTES);
    SPLIT_STORE2(rv2, smb + so2, smb + so2 + SEC_BYTES);
    SPLIT_STORE2(rv3, smb + so3, smb + so3 + SEC_BYTES);

    const uint32_t a_roff = (uint32_t)(wm + (lane & 15)) * RSB
                          + (uint32_t)((lane >> 4) * 16);
    const uint32_t b_roff = 2u * SEC_BYTES
                          + (uint32_t)(wn + (lane & 7) + ((lane >> 4) << 3)) * RSB
                          + (uint32_t)(((lane >> 3) & 1) * 16);

    for (int ch = 0; ch < NCH; ++ch) {
        const uint32_t sb  = smb + (uint32_t)(ch & 1) * STAGE_BYTES;
        const uint32_t sb2 = smb + (uint32_t)((ch & 1) ^ 1) * STAGE_BYTES;
        __syncthreads();

        if (ch + 1 < NCH) {
            const int k0 = (ch + 1) * KC;
            rv0 = *(const float4*)(gp0 + k0);
            rv1 = *(const float4*)(gp1 + k0);
            rv2 = *(const float4*)(gp2 + k0);
            rv3 = *(const float4*)(gp3 + k0);
        }

        uint32_t ah[4][4], al[4][4];
#pragma unroll
        for (int mt = 0; mt < 4; ++mt) {
            uint32_t ad = sb + a_roff + (uint32_t)(mt * 16) * RSB;
            LDSM4(ah[mt][0], ah[mt][1], ah[mt][2], ah[mt][3], ad);
            LDSM4(al[mt][0], al[mt][1], al[mt][2], al[mt][3], ad + SEC_BYTES);
        }
#pragma unroll
        for (int p = 0; p < 2; ++p) {
            uint32_t bh[4], bl[4];
            uint32_t bd = sb + b_roff + (uint32_t)(p * 16) * RSB;
            LDSM4(bh[0], bh[1], bh[2], bh[3], bd);
            LDSM4(bl[0], bl[1], bl[2], bl[3], bd + SEC_BYTES);
#pragma unroll
            for (int mt = 0; mt < 4; ++mt) {
#pragma unroll
                for (int q = 0; q < 2; ++q) {
                    const int nt = p * 2 + q;
                    MMA_BF16(acc[mt][nt][0], acc[mt][nt][1],
                             acc[mt][nt][2], acc[mt][nt][3],
                             ah[mt][0], ah[mt][1], ah[mt][2], ah[mt][3],
                             bh[2*q], bh[2*q+1]);
                    MMA_BF16(acc[mt][nt][0], acc[mt][nt][1],
                             acc[mt][nt][2], acc[mt][nt][3],
                             al[mt][0], al[mt][1], al[mt][2], al[mt][3],
                             bh[2*q], bh[2*q+1]);
                    MMA_BF16(acc[mt][nt][0], acc[mt][nt][1],
                             acc[mt][nt][2], acc[mt][nt][3],
                             ah[mt][0], ah[mt][1], ah[mt][2], ah[mt][3],
                             bl[2*q], bl[2*q+1]);
                }
            }
        }

        if (ch + 1 < NCH) {
            SPLIT_STORE2(rv0, sb2 + so0, sb2 + so0 + SEC_BYTES);
            SPLIT_STORE2(rv1, sb2 + so1, sb2 + so1 + SEC_BYTES);
            SPLIT_STORE2(rv2, sb2 + so2, sb2 + so2 + SEC_BYTES);
            SPLIT_STORE2(rv3, sb2 + so3, sb2 + so3 + SEC_BYTES);
        }
    }

    float* qkv = (mode == 0) ? g_q : (mode == 1) ? g_k : g_v;
#pragma unroll
    for (int mt = 0; mt < 4; ++mt) {
#pragma unroll
        for (int nt = 0; nt < 4; ++nt) {
            const int gn = n0 + wn + nt * 8 + (lane & 3) * 2;
            const float b0 = bias[gn], b1 = bias[gn + 1];
#pragma unroll
            for (int h2 = 0; h2 < 2; ++h2) {
                const int gm = m0 + wm + mt * 16 + h2 * 8 + (lane >> 2);
                float2 v;
                v.x = acc[mt][nt][h2 * 2 + 0] + b0;
                v.y = acc[mt][nt][h2 * 2 + 1] + b1;
                if (mode <= 2) {
                    int bb = gm >> 12, ss = gm & 4095;
                    int hh = gn >> 6,  dd = gn & 63;
                    *(float2*)&qkv[((((size_t)bb * NHn + hh) * Sn) + ss) * HDn + dd] = v;
                } else {
                    *(float2*)&outp[(size_t)gm * HIDn + gn] = v;
                }
            }
        }
    }
}

// ---------------- fp16 2-term GEMM (V and O) --------------------------------
__global__ void __launch_bounds__(256) gemm_f16(const float* __restrict__ A,
                                                const float* __restrict__ Wt,
                                                const float* __restrict__ bias,
                                                float* __restrict__ outp, int mode)
{
    __shared__ __align__(1024) char smem_buf[F_SMEM];
    const uint32_t smb = (uint32_t)__cvta_generic_to_shared(smem_buf);

    const int tid  = threadIdx.x;
    const int lane = tid & 31;
    const int wid  = tid >> 5;
    const int wm   = (wid >> 2) * 64;
    const int wn   = (wid & 3) * 32;
    const int n0   = blockIdx.x * BN;
    const int m0   = blockIdx.y * BM;

    const float* Asrc = (mode == 3) ? g_ctx : A;

    const int r0 = tid >> 2;
    const int cq = tid & 3;
    const float* gp0 = Asrc + (size_t)(m0 + r0) * Kn + cq * 4;
    const float* gp1 = gp0 + (size_t)64 * Kn;
    const float* gp2 = Wt + (size_t)(n0 + r0) * Kn + cq * 4;
    const float* gp3 = gp2 + (size_t)64 * Kn;
    const uint32_t rcq = (uint32_t)(r0 * RSB + cq * 8);
    const uint32_t so0 = rcq;
    const uint32_t so1 = rcq + 64u * RSB;
    const uint32_t so2 = 2u * SEC_BYTES + rcq;
    const uint32_t so3 = 2u * SEC_BYTES + rcq + 64u * RSB;

    float acc[4][4][4];
#pragma unroll
    for (int a = 0; a < 4; ++a)
#pragma unroll
        for (int b = 0; b < 4; ++b)
#pragma unroll
            for (int c = 0; c < 4; ++c) acc[a][b][c] = 0.f;

    float4 rv0 = *(const float4*)gp0;
    float4 rv1 = *(const float4*)gp1;
    float4 rv2 = *(const float4*)gp2;
    float4 rv3 = *(const float4*)gp3;
    SPLIT_STORE2_F16(rv0, smb + so0, smb + so0 + SEC_BYTES);
    SPLIT_STORE2_F16(rv1, smb + so1, smb + so1 + SEC_BYTES);
    CVT_STORE_F16(rv2, smb + so2);
    CVT_STORE_F16(rv3, smb + so3);

    const uint32_t a_roff = (uint32_t)(wm + (lane & 15)) * RSB
                          + (uint32_t)((lane >> 4) * 16);
    const uint32_t b_roff = 2u * SEC_BYTES
                          + (uint32_t)(wn + (lane & 7) + ((lane >> 4) << 3)) * RSB
                          + (uint32_t)(((lane >> 3) & 1) * 16);

    for (int ch = 0; ch < NCH; ++ch) {
        const uint32_t sb  = smb + (uint32_t)(ch & 1) * F_STAGE;
        const uint32_t sb2 = smb + (uint32_t)((ch & 1) ^ 1) * F_STAGE;
        __syncthreads();

        if (ch + 1 < NCH) {
            const int k0 = (ch + 1) * KC;
            rv0 = *(const float4*)(gp0 + k0);
            rv1 = *(const float4*)(gp1 + k0);
            rv2 = *(const float4*)(gp2 + k0);
            rv3 = *(const float4*)(gp3 + k0);
        }

        uint32_t ah[4][4], al[4][4];
#pragma unroll
        for (int mt = 0; mt < 4; ++mt) {
            uint32_t ad = sb + a_roff + (uint32_t)(mt * 16) * RSB;
            LDSM4(ah[mt][0], ah[mt][1], ah[mt][2], ah[mt][3], ad);
            LDSM4(al[mt][0], al[mt][1], al[mt][2], al[mt][3], ad + SEC_BYTES);
        }
#pragma unroll
        for (int p = 0; p < 2; ++p) {
            uint32_t bh[4];
            uint32_t bd = sb + b_roff + (uint32_t)(p * 16) * RSB;
            LDSM4(bh[0], bh[1], bh[2], bh[3], bd);
#pragma unroll
            for (int mt = 0; mt < 4; ++mt) {
#pragma unroll
                for (int q = 0; q < 2; ++q) {
                    const int nt = p * 2 + q;
                    MMA_F16(acc[mt][nt][0], acc[mt][nt][1],
                            acc[mt][nt][2], acc[mt][nt][3],
                            ah[mt][0], ah[mt][1], ah[mt][2], ah[mt][3],
                            bh[2*q], bh[2*q+1]);
                    MMA_F16(acc[mt][nt][0], acc[mt][nt][1],
                            acc[mt][nt][2], acc[mt][nt][3],
                            al[mt][0], al[mt][1], al[mt][2], al[mt][3],
                            bh[2*q], bh[2*q+1]);
                }
            }
        }

        if (ch + 1 < NCH) {
            SPLIT_STORE2_F16(rv0, sb2 + so0, sb2 + so0 + SEC_BYTES);
            SPLIT_STORE2_F16(rv1, sb2 + so1, sb2 + so1 + SEC_BYTES);
            CVT_STORE_F16(rv2, sb2 + so2);
            CVT_STORE_F16(rv3, sb2 + so3);
        }
    }

#pragma unroll
    for (int mt = 0; mt < 4; ++mt) {
#pragma unroll
        for (int nt = 0; nt < 4; ++nt) {
            const int gn = n0 + wn + nt * 8 + (lane & 3) * 2;
            const float b0 = bias[gn], b1 = bias[gn + 1];
#pragma unroll
            for (int h2 = 0; h2 < 2; ++h2) {
                const int gm = m0 + wm + mt * 16 + h2 * 8 + (lane >> 2);
                float2 v;
                v.x = acc[mt][nt][h2 * 2 + 0] + b0;
                v.y = acc[mt][nt][h2 * 2 + 1] + b1;
                if (mode == 2) {
                    int bb = gm >> 12, ss = gm & 4095;
                    int hh = gn >> 6,  dd = gn & 63;
                    *(float2*)&g_v[((((size_t)bb * NHn + hh) * Sn) + ss) * HDn + dd] = v;
                } else {
                    *(float2*)&outp[(size_t)gm * HIDn + gn] = v;
                }
            }
        }
    }
}

// ---------------- RoPE (in place on g_q, g_k) ------------------------------
__global__ void rope_kernel()
{
    int t   = blockIdx.x * blockDim.x + threadIdx.x;
    int i   = t & 31;
    int row = t >> 5;
    int s   = row & (Sn - 1);

    double e = -(double)i * (9.210340371976184 / 32.0);
    float inv = (float)exp(e);
    float ang = (float)s * inv;
    float si, co;
    sincosf(ang, &si, &co);

    long base = (long)row * HDn;
    float x1 = g_q[base + i], x2 = g_q[base + i + 32];
    g_q[base + i]      = x1 * co - x2 * si;
    g_q[base + i + 32] = x2 * co + x1 * si;
    float y1 = g_k[base + i], y2 = g_k[base + i + 32];
    g_k[base + i]      = y1 * co - y2 * si;
    g_k[base + i + 32] = y2 * co + y1 * si;
}

// ---------------- banded attention -----------------------------------------
__global__ __launch_bounds__(128) void attn_kernel()
{
    __shared__ float smem_pool[8192];

    const int n  = blockIdx.x;
    const int h  = blockIdx.y;
    const int b  = blockIdx.z;
    const int qi = threadIdx.x;
    const int tid = threadIdx.x;

    const long headbase = ((long)(b * NHn + h)) * Sn;

    const float* qbase = g_q + (headbase + (long)n * Wn) * HDn;
    for (int i = tid; i < 2048; i += 128)
        ((float4*)smem_pool)[i] = ((const float4*)qbase)[i];
    __syncthreads();
    float rq[64];
#pragma unroll
    for (int d = 0; d < 64; ++d) rq[d] = smem_pool[qi * 64 + d];

    float m = NEG_BIG, l = 0.f;
    float acc[64];
#pragma unroll
    for (int d = 0; d < 64; ++d) acc[d] = 0.f;

    const int first_chunk = (n == 0) ? 2 : 0;

    for (int c = first_chunk; c < 4; ++c) {
        long krow0 = headbase + (long)((n - 1) * Wn + c * 64);
        const float* kb = g_k + krow0 * HDn;
        const float* vb = g_v + krow0 * HDn;
        __syncthreads();
        for (int i = tid; i < 1024; i += 128) {
            ((float4*)smem_pool)[i]        = ((const float4*)kb)[i];
            ((float4*)smem_pool)[1024 + i] = ((const float4*)vb)[i];
        }
        __syncthreads();

        for (int jt = 0; jt < 4; ++jt) {
            const int kj0 = c * 64 + jt * 16;
            float sc[16];
            float mx = NEG_BIG;
#pragma unroll
            for (int j = 0; j < 16; ++j) {
                int kj = kj0 + j;
                bool valid = (kj >= qi) && (kj <= qi + Wn);
                float s_ = NEG_BIG;
                if (valid) {
                    const float* kr = &smem_pool[(kj - c * 64) * 64];
                    float dot = 0.f;
#pragma unroll
                    for (int d = 0; d < 64; d += 4) {
                        float4 kv = *(const float4*)&kr[d];
                        dot += rq[d] * kv.x + rq[d+1] * kv.y
                             + rq[d+2] * kv.z + rq[d+3] * kv.w;
                    }
                    s_ = dot * 0.125f;
                }
                sc[j] = s_;
                mx = fmaxf(mx, s_);
            }
            float newm = fmaxf(m, mx);
            if (newm > NEG_BIG) {
                if (newm > m) {                 // rescale only when max moved
                    float f = __expf(m - newm);
                    l *= f;
#pragma unroll
                    for (int d = 0; d < 64; ++d) acc[d] *= f;
                    m = newm;
                }
#pragma unroll
                for (int j = 0; j < 16; ++j) {
                    if (sc[j] > NEG_BIG) {
                        float p = __expf(sc[j] - m);
                        l += p;
                        const float* vr = &smem_pool[4096 + (kj0 + j - c * 64) * 64];
#pragma unroll
                        for (int d = 0; d < 64; d += 4) {
                            float4 vv = *(const float4*)&vr[d];
                            acc[d]   += p * vv.x; acc[d+1] += p * vv.y;
                            acc[d+2] += p * vv.z; acc[d+3] += p * vv.w;
                        }
                    }
                }
            }
        }
    }

    __syncthreads();
    float invl = 1.f / l;
#pragma unroll
    for (int d = 0; d < 64; ++d) smem_pool[qi * 64 + d] = acc[d] * invl;
    __syncthreads();

    float* obase = g_ctx + ((long)b * Sn + (long)n * Wn) * HIDn + h * HDn;
    for (int i = tid; i < 2048; i += 128) {
        int r  = i >> 4;
        int dq = i & 15;
        ((float4*)(obase + (long)r * HIDn))[dq] = ((const float4*)smem_pool)[i];
    }
}

// ---------------- launch (reordered: V GEMM at slot 4 for ncu capture) ------
extern "C" void kernel_launch(void* const* d_in, const int* in_sizes, int n_in,
                              void* d_out, int out_size)
{
    const float* X  = (const float*)d_in[0];
    const float* Wq = (const float*)d_in[1];
    const float* bq = (const float*)d_in[2];
    const float* Wk = (const float*)d_in[3];
    const float* bk = (const float*)d_in[4];
    const float* Wv = (const float*)d_in[5];
    const float* bv = (const float*)d_in[6];
    const float* Wo = (const float*)d_in[7];
    const float* bo = (const float*)d_in[8];
    float* out = (float*)d_out;

    dim3 gg(HIDn / BN, Mn / BM);   // (8, 64)
    gemm_mma<<<gg, 256>>>(X, Wq, bq, nullptr, 0);   // 1: Q (bf16 3-term)
    gemm_mma<<<gg, 256>>>(X, Wk, bk, nullptr, 1);   // 2: K (bf16 3-term)

    rope_kernel<<<(Bn * NHn * Sn * 32) / 256, 256>>>();  // 3: rope (needs Q,K)

    gemm_f16<<<gg, 256>>>(X, Wv, bv, nullptr, 2);   // 4: V (fp16 2-term) <- ncu slot

    dim3 ag(NBLK, NHn, Bn);
    attn_kernel<<<ag, 128>>>();                     // 5: attention

    gemm_f16<<<gg, 256>>>(nullptr, Wo, bo, out, 3); // 6: O (fp16 2-term)
}

// round 16
// speedup vs baseline: 1.1918x; 1.1270x over previous
#include <cuda_runtime.h>
#include <cuda_bf16.h>
#include <math.h>
#include <stdint.h>

#define Bn   2
#define Sn   4096
#define HIDn 1024
#define NHn  16
#define HDn  64
#define Wn   128
#define Mn   (Bn * Sn)          // 8192 rows
#define Kn   1024
#define NBLK (Sn / Wn)          // 32 query blocks
#define NEG_BIG (-3.402823466e38f)

// GEMM tile config: 128x128 CTA, 64x32 warp tile, KC=16, 2 CTAs/SM target
#define BM 128
#define BN 128
#define KC 16
#define NCH (Kn / KC)            // 64 stages
#define RSB 48                   // padded row stride in BYTES
#define SEC_BYTES (128 * RSB)    // 6144
#define STAGE_BYTES (4 * SEC_BYTES)   // 24576 (bf16 3-term: Ah|Al|Wh|Wl)
#define SMEM_TOTAL (2 * STAGE_BYTES)  // 49152 static
#define F_STAGE (3 * SEC_BYTES)       // 18432 (fp16 2-term: Ah|Al|W)
#define F_SMEM (2 * F_STAGE)          // 36864 static

// ---------------- scratch: EXACTLY the proven 128MiB static set -------------
__device__ float g_q[Bn * NHn * Sn * HDn];
__device__ float g_k[Bn * NHn * Sn * HDn];
__device__ float g_v[Bn * NHn * Sn * HDn];
__device__ float g_ctx[Mn * HIDn];

// ---------------- macros ----------------------------------------------------
#define LDSM4(d0, d1, d2, d3, ad)                                              \
    asm volatile("ldmatrix.sync.aligned.m8n8.x4.shared.b16 {%0,%1,%2,%3}, [%4];" \
                 : "=r"(d0), "=r"(d1), "=r"(d2), "=r"(d3) : "r"(ad))

#define MMA_BF16(c0, c1, c2, c3, a0, a1, a2, a3, b0, b1)                       \
    asm volatile("mma.sync.aligned.m16n8k16.row.col.f32.bf16.bf16.f32 "        \
                 "{%0,%1,%2,%3}, {%4,%5,%6,%7}, {%8,%9}, {%0,%1,%2,%3};"        \
                 : "+f"(c0), "+f"(c1), "+f"(c2), "+f"(c3)                       \
                 : "r"(a0), "r"(a1), "r"(a2), "r"(a3), "r"(b0), "r"(b1))

#define MMA_F16(c0, c1, c2, c3, a0, a1, a2, a3, b0, b1)                        \
    asm volatile("mma.sync.aligned.m16n8k16.row.col.f32.f16.f16.f32 "          \
                 "{%0,%1,%2,%3}, {%4,%5,%6,%7}, {%8,%9}, {%0,%1,%2,%3};"        \
                 : "+f"(c0), "+f"(c1), "+f"(c2), "+f"(c3)                       \
                 : "r"(a0), "r"(a1), "r"(a2), "r"(a3), "r"(b0), "r"(b1))

#define CVT_SPLIT(v, h01, h23, l01, l23)                                       \
    do {                                                                       \
        asm("cvt.rn.bf16x2.f32 %0, %1, %2;" : "=r"(h01) : "f"((v).y), "f"((v).x)); \
        asm("cvt.rn.bf16x2.f32 %0, %1, %2;" : "=r"(h23) : "f"((v).w), "f"((v).z)); \
        float r0_ = (v).x - __uint_as_float((h01) << 16);                      \
        float r1_ = (v).y - __uint_as_float((h01) & 0xFFFF0000u);              \
        float r2_ = (v).z - __uint_as_float((h23) << 16);                      \
        float r3_ = (v).w - __uint_as_float((h23) & 0xFFFF0000u);              \
        asm("cvt.rn.bf16x2.f32 %0, %1, %2;" : "=r"(l01) : "f"(r1_), "f"(r0_)); \
        asm("cvt.rn.bf16x2.f32 %0, %1, %2;" : "=r"(l23) : "f"(r3_), "f"(r2_)); \
    } while (0)

#define SPLIT_STORE2(v, ah_, al_)                                              \
    do {                                                                       \
        uint32_t h01_, h23_, l01_, l23_;                                       \
        CVT_SPLIT(v, h01_, h23_, l01_, l23_);                                  \
        asm volatile("st.shared.v2.b32 [%0], {%1,%2};"                         \
                     :: "r"(ah_), "r"(h01_), "r"(h23_) : "memory");            \
        asm volatile("st.shared.v2.b32 [%0], {%1,%2};"                         \
                     :: "r"(al_), "r"(l01_), "r"(l23_) : "memory");            \
    } while (0)

#define CVT_SPLIT_F16(v, h01, h23, l01, l23)                                   \
    do {                                                                       \
        asm("cvt.rn.f16x2.f32 %0, %1, %2;" : "=r"(h01) : "f"((v).y), "f"((v).x)); \
        asm("cvt.rn.f16x2.f32 %0, %1, %2;" : "=r"(h23) : "f"((v).w), "f"((v).z)); \
        float b0_, b1_, b2_, b3_;                                              \
        asm("{.reg .f16 l_,h_; mov.b32 {l_,h_}, %2; cvt.f32.f16 %0, l_; "      \
            "cvt.f32.f16 %1, h_;}" : "=f"(b0_), "=f"(b1_) : "r"(h01));         \
        asm("{.reg .f16 l_,h_; mov.b32 {l_,h_}, %2; cvt.f32.f16 %0, l_; "      \
            "cvt.f32.f16 %1, h_;}" : "=f"(b2_), "=f"(b3_) : "r"(h23));         \
        float r0_ = (v).x - b0_, r1_ = (v).y - b1_;                            \
        float r2_ = (v).z - b2_, r3_ = (v).w - b3_;                            \
        asm("cvt.rn.f16x2.f32 %0, %1, %2;" : "=r"(l01) : "f"(r1_), "f"(r0_)); \
        asm("cvt.rn.f16x2.f32 %0, %1, %2;" : "=r"(l23) : "f"(r3_), "f"(r2_)); \
    } while (0)

#define SPLIT_STORE2_F16(v, ah_, al_)                                          \
    do {                                                                       \
        uint32_t h01_, h23_, l01_, l23_;                                       \
        CVT_SPLIT_F16(v, h01_, h23_, l01_, l23_);                              \
        asm volatile("st.shared.v2.b32 [%0], {%1,%2};"                         \
                     :: "r"(ah_), "r"(h01_), "r"(h23_) : "memory");            \
        asm volatile("st.shared.v2.b32 [%0], {%1,%2};"                         \
                     :: "r"(al_), "r"(l01_), "r"(l23_) : "memory");            \
    } while (0)

#define CVT_STORE_F16(v, aw_)                                                  \
    do {                                                                       \
        uint32_t h01_, h23_;                                                   \
        asm("cvt.rn.f16x2.f32 %0, %1, %2;" : "=r"(h01_) : "f"((v).y), "f"((v).x)); \
        asm("cvt.rn.f16x2.f32 %0, %1, %2;" : "=r"(h23_) : "f"((v).w), "f"((v).z)); \
        asm volatile("st.shared.v2.b32 [%0], {%1,%2};"                         \
                     :: "r"(aw_), "r"(h01_), "r"(h23_) : "memory");            \
    } while (0)

// ---------------- bf16 3-term GEMM (Q and K), reg-lean, 2 CTAs/SM -----------
__global__ void __launch_bounds__(256, 2) gemm_mma(const float* __restrict__ A,
                                                   const float* __restrict__ Wt,
                                                   const float* __restrict__ bias,
                                                   float* __restrict__ outp, int mode)
{
    __shared__ __align__(1024) char smem_buf[SMEM_TOTAL];
    const uint32_t smb = (uint32_t)__cvta_generic_to_shared(smem_buf);

    const int tid  = threadIdx.x;
    const int lane = tid & 31;
    const int wid  = tid >> 5;
    const int wm   = (wid >> 2) * 64;
    const int wn   = (wid & 3) * 32;
    const int n0   = blockIdx.x * BN;
    const int m0   = blockIdx.y * BM;

    const float* Asrc = (mode == 3) ? g_ctx : A;

    const int r0 = tid >> 2;
    const int cq = tid & 3;
    const float* gp0 = Asrc + (size_t)(m0 + r0) * Kn + cq * 4;
    const float* gp1 = gp0 + (size_t)64 * Kn;
    const float* gp2 = Wt + (size_t)(n0 + r0) * Kn + cq * 4;
    const float* gp3 = gp2 + (size_t)64 * Kn;
    const uint32_t rcq = (uint32_t)(r0 * RSB + cq * 8);
    const uint32_t so0 = rcq;
    const uint32_t so1 = rcq + 64u * RSB;
    const uint32_t so2 = 2u * SEC_BYTES + rcq;
    const uint32_t so3 = 2u * SEC_BYTES + rcq + 64u * RSB;

    float acc[4][4][4];
#pragma unroll
    for (int a = 0; a < 4; ++a)
#pragma unroll
        for (int b = 0; b < 4; ++b)
#pragma unroll
            for (int c = 0; c < 4; ++c) acc[a][b][c] = 0.f;

    float4 rv0 = *(const float4*)gp0;
    float4 rv1 = *(const float4*)gp1;
    float4 rv2 = *(const float4*)gp2;
    float4 rv3 = *(const float4*)gp3;
    SPLIT_STORE2(rv0, smb + so0, smb + so0 + SEC_BYTES);
    SPLIT_STORE2(rv1, smb + so1, smb + so1 + SEC_BYTES);
    SPLIT_STORE2(rv2, smb + so2, smb + so2 + SEC_BYTES);
    SPLIT_STORE2(rv3, smb + so3, smb + so3 + SEC_BYTES);

    const uint32_t a_roff = (uint32_t)(wm + (lane & 15)) * RSB
                          + (uint32_t)((lane >> 4) * 16);
    const uint32_t b_roff = 2u * SEC_BYTES
                          + (uint32_t)(wn + (lane & 7) + ((lane >> 4) << 3)) * RSB
                          + (uint32_t)(((lane >> 3) & 1) * 16);

    for (int ch = 0; ch < NCH; ++ch) {
        const uint32_t sb  = smb + (uint32_t)(ch & 1) * STAGE_BYTES;
        const uint32_t sb2 = smb + (uint32_t)((ch & 1) ^ 1) * STAGE_BYTES;
        __syncthreads();

        if (ch + 1 < NCH) {
            const int k0 = (ch + 1) * KC;
            rv0 = *(const float4*)(gp0 + k0);
            rv1 = *(const float4*)(gp1 + k0);
            rv2 = *(const float4*)(gp2 + k0);
            rv3 = *(const float4*)(gp3 + k0);
        }

        // B fragments up-front (16 regs), A per-mt (8 regs live)
        uint32_t bh[2][4], bl[2][4];
#pragma unroll
        for (int p = 0; p < 2; ++p) {
            uint32_t bd = sb + b_roff + (uint32_t)(p * 16) * RSB;
            LDSM4(bh[p][0], bh[p][1], bh[p][2], bh[p][3], bd);
            LDSM4(bl[p][0], bl[p][1], bl[p][2], bl[p][3], bd + SEC_BYTES);
        }
#pragma unroll
        for (int mt = 0; mt < 4; ++mt) {
            uint32_t ah[4], al[4];
            uint32_t ad = sb + a_roff + (uint32_t)(mt * 16) * RSB;
            LDSM4(ah[0], ah[1], ah[2], ah[3], ad);
            LDSM4(al[0], al[1], al[2], al[3], ad + SEC_BYTES);
#pragma unroll
            for (int p = 0; p < 2; ++p) {
#pragma unroll
                for (int q = 0; q < 2; ++q) {
                    const int nt = p * 2 + q;
                    MMA_BF16(acc[mt][nt][0], acc[mt][nt][1],
                             acc[mt][nt][2], acc[mt][nt][3],
                             ah[0], ah[1], ah[2], ah[3],
                             bh[p][2*q], bh[p][2*q+1]);
                    MMA_BF16(acc[mt][nt][0], acc[mt][nt][1],
                             acc[mt][nt][2], acc[mt][nt][3],
                             al[0], al[1], al[2], al[3],
                             bh[p][2*q], bh[p][2*q+1]);
                    MMA_BF16(acc[mt][nt][0], acc[mt][nt][1],
                             acc[mt][nt][2], acc[mt][nt][3],
                             ah[0], ah[1], ah[2], ah[3],
                             bl[p][2*q], bl[p][2*q+1]);
                }
            }
        }

        if (ch + 1 < NCH) {
            SPLIT_STORE2(rv0, sb2 + so0, sb2 + so0 + SEC_BYTES);
            SPLIT_STORE2(rv1, sb2 + so1, sb2 + so1 + SEC_BYTES);
            SPLIT_STORE2(rv2, sb2 + so2, sb2 + so2 + SEC_BYTES);
            SPLIT_STORE2(rv3, sb2 + so3, sb2 + so3 + SEC_BYTES);
        }
    }

    float* qkv = (mode == 0) ? g_q : (mode == 1) ? g_k : g_v;
#pragma unroll
    for (int mt = 0; mt < 4; ++mt) {
#pragma unroll
        for (int nt = 0; nt < 4; ++nt) {
            const int gn = n0 + wn + nt * 8 + (lane & 3) * 2;
            const float b0 = bias[gn], b1 = bias[gn + 1];
#pragma unroll
            for (int h2 = 0; h2 < 2; ++h2) {
                const int gm = m0 + wm + mt * 16 + h2 * 8 + (lane >> 2);
                float2 v;
                v.x = acc[mt][nt][h2 * 2 + 0] + b0;
                v.y = acc[mt][nt][h2 * 2 + 1] + b1;
                if (mode <= 2) {
                    int bb = gm >> 12, ss = gm & 4095;
                    int hh = gn >> 6,  dd = gn & 63;
                    *(float2*)&qkv[((((size_t)bb * NHn + hh) * Sn) + ss) * HDn + dd] = v;
                } else {
                    *(float2*)&outp[(size_t)gm * HIDn + gn] = v;
                }
            }
        }
    }
}

// ---------------- fp16 2-term GEMM (V and O), reg-lean, 2 CTAs/SM -----------
__global__ void __launch_bounds__(256, 2) gemm_f16(const float* __restrict__ A,
                                                   const float* __restrict__ Wt,
                                                   const float* __restrict__ bias,
                                                   float* __restrict__ outp, int mode)
{
    __shared__ __align__(1024) char smem_buf[F_SMEM];
    const uint32_t smb = (uint32_t)__cvta_generic_to_shared(smem_buf);

    const int tid  = threadIdx.x;
    const int lane = tid & 31;
    const int wid  = tid >> 5;
    const int wm   = (wid >> 2) * 64;
    const int wn   = (wid & 3) * 32;
    const int n0   = blockIdx.x * BN;
    const int m0   = blockIdx.y * BM;

    const float* Asrc = (mode == 3) ? g_ctx : A;

    const int r0 = tid >> 2;
    const int cq = tid & 3;
    const float* gp0 = Asrc + (size_t)(m0 + r0) * Kn + cq * 4;
    const float* gp1 = gp0 + (size_t)64 * Kn;
    const float* gp2 = Wt + (size_t)(n0 + r0) * Kn + cq * 4;
    const float* gp3 = gp2 + (size_t)64 * Kn;
    const uint32_t rcq = (uint32_t)(r0 * RSB + cq * 8);
    const uint32_t so0 = rcq;
    const uint32_t so1 = rcq + 64u * RSB;
    const uint32_t so2 = 2u * SEC_BYTES + rcq;
    const uint32_t so3 = 2u * SEC_BYTES + rcq + 64u * RSB;

    float acc[4][4][4];
#pragma unroll
    for (int a = 0; a < 4; ++a)
#pragma unroll
        for (int b = 0; b < 4; ++b)
#pragma unroll
            for (int c = 0; c < 4; ++c) acc[a][b][c] = 0.f;

    float4 rv0 = *(const float4*)gp0;
    float4 rv1 = *(const float4*)gp1;
    float4 rv2 = *(const float4*)gp2;
    float4 rv3 = *(const float4*)gp3;
    SPLIT_STORE2_F16(rv0, smb + so0, smb + so0 + SEC_BYTES);
    SPLIT_STORE2_F16(rv1, smb + so1, smb + so1 + SEC_BYTES);
    CVT_STORE_F16(rv2, smb + so2);
    CVT_STORE_F16(rv3, smb + so3);

    const uint32_t a_roff = (uint32_t)(wm + (lane & 15)) * RSB
                          + (uint32_t)((lane >> 4) * 16);
    const uint32_t b_roff = 2u * SEC_BYTES
                          + (uint32_t)(wn + (lane & 7) + ((lane >> 4) << 3)) * RSB
                          + (uint32_t)(((lane >> 3) & 1) * 16);

    for (int ch = 0; ch < NCH; ++ch) {
        const uint32_t sb  = smb + (uint32_t)(ch & 1) * F_STAGE;
        const uint32_t sb2 = smb + (uint32_t)((ch & 1) ^ 1) * F_STAGE;
        __syncthreads();

        if (ch + 1 < NCH) {
            const int k0 = (ch + 1) * KC;
            rv0 = *(const float4*)(gp0 + k0);
            rv1 = *(const float4*)(gp1 + k0);
            rv2 = *(const float4*)(gp2 + k0);
            rv3 = *(const float4*)(gp3 + k0);
        }

        // B fragments up-front (8 regs), A per-mt (8 regs live)
        uint32_t bh[2][4];
#pragma unroll
        for (int p = 0; p < 2; ++p) {
            uint32_t bd = sb + b_roff + (uint32_t)(p * 16) * RSB;
            LDSM4(bh[p][0], bh[p][1], bh[p][2], bh[p][3], bd);
        }
#pragma unroll
        for (int mt = 0; mt < 4; ++mt) {
            uint32_t ah[4], al[4];
            uint32_t ad = sb + a_roff + (uint32_t)(mt * 16) * RSB;
            LDSM4(ah[0], ah[1], ah[2], ah[3], ad);
            LDSM4(al[0], al[1], al[2], al[3], ad + SEC_BYTES);
#pragma unroll
            for (int p = 0; p < 2; ++p) {
#pragma unroll
                for (int q = 0; q < 2; ++q) {
                    const int nt = p * 2 + q;
                    MMA_F16(acc[mt][nt][0], acc[mt][nt][1],
                            acc[mt][nt][2], acc[mt][nt][3],
                            ah[0], ah[1], ah[2], ah[3],
                            bh[p][2*q], bh[p][2*q+1]);
                    MMA_F16(acc[mt][nt][0], acc[mt][nt][1],
                            acc[mt][nt][2], acc[mt][nt][3],
                            al[0], al[1], al[2], al[3],
                            bh[p][2*q], bh[p][2*q+1]);
                }
            }
        }

        if (ch + 1 < NCH) {
            SPLIT_STORE2_F16(rv0, sb2 + so0, sb2 + so0 + SEC_BYTES);
            SPLIT_STORE2_F16(rv1, sb2 + so1, sb2 + so1 + SEC_BYTES);
            CVT_STORE_F16(rv2, sb2 + so2);
            CVT_STORE_F16(rv3, sb2 + so3);
        }
    }

#pragma unroll
    for (int mt = 0; mt < 4; ++mt) {
#pragma unroll
        for (int nt = 0; nt < 4; ++nt) {
            const int gn = n0 + wn + nt * 8 + (lane & 3) * 2;
            const float b0 = bias[gn], b1 = bias[gn + 1];
#pragma unroll
            for (int h2 = 0; h2 < 2; ++h2) {
                const int gm = m0 + wm + mt * 16 + h2 * 8 + (lane >> 2);
                float2 v;
                v.x = acc[mt][nt][h2 * 2 + 0] + b0;
                v.y = acc[mt][nt][h2 * 2 + 1] + b1;
                if (mode == 2) {
                    int bb = gm >> 12, ss = gm & 4095;
                    int hh = gn >> 6,  dd = gn & 63;
                    *(float2*)&g_v[((((size_t)bb * NHn + hh) * Sn) + ss) * HDn + dd] = v;
                } else {
                    *(float2*)&outp[(size_t)gm * HIDn + gn] = v;
                }
            }
        }
    }
}

// ---------------- RoPE (in place on g_q, g_k) ------------------------------
__global__ void rope_kernel()
{
    int t   = blockIdx.x * blockDim.x + threadIdx.x;
    int i   = t & 31;
    int row = t >> 5;
    int s   = row & (Sn - 1);

    double e = -(double)i * (9.210340371976184 / 32.0);
    float inv = (float)exp(e);
    float ang = (float)s * inv;
    float si, co;
    sincosf(ang, &si, &co);

    long base = (long)row * HDn;
    float x1 = g_q[base + i], x2 = g_q[base + i + 32];
    g_q[base + i]      = x1 * co - x2 * si;
    g_q[base + i + 32] = x2 * co + x1 * si;
    float y1 = g_k[base + i], y2 = g_k[base + i + 32];
    g_k[base + i]      = y1 * co - y2 * si;
    g_k[base + i + 32] = y2 * co + y1 * si;
}

// ---------------- banded attention -----------------------------------------
__global__ __launch_bounds__(128) void attn_kernel()
{
    __shared__ float smem_pool[8192];

    const int n  = blockIdx.x;
    const int h  = blockIdx.y;
    const int b  = blockIdx.z;
    const int qi = threadIdx.x;
    const int tid = threadIdx.x;

    const long headbase = ((long)(b * NHn + h)) * Sn;

    const float* qbase = g_q + (headbase + (long)n * Wn) * HDn;
    for (int i = tid; i < 2048; i += 128)
        ((float4*)smem_pool)[i] = ((const float4*)qbase)[i];
    __syncthreads();
    float rq[64];
#pragma unroll
    for (int d = 0; d < 64; ++d) rq[d] = smem_pool[qi * 64 + d];

    float m = NEG_BIG, l = 0.f;
    float acc[64];
#pragma unroll
    for (int d = 0; d < 64; ++d) acc[d] = 0.f;

    const int first_chunk = (n == 0) ? 2 : 0;

    for (int c = first_chunk; c < 4; ++c) {
        long krow0 = headbase + (long)((n - 1) * Wn + c * 64);
        const float* kb = g_k + krow0 * HDn;
        const float* vb = g_v + krow0 * HDn;
        __syncthreads();
        for (int i = tid; i < 1024; i += 128) {
            ((float4*)smem_pool)[i]        = ((const float4*)kb)[i];
            ((float4*)smem_pool)[1024 + i] = ((const float4*)vb)[i];
        }
        __syncthreads();

        for (int jt = 0; jt < 4; ++jt) {
            const int kj0 = c * 64 + jt * 16;
            float sc[16];
            float mx = NEG_BIG;
#pragma unroll
            for (int j = 0; j < 16; ++j) {
                int kj = kj0 + j;
                bool valid = (kj >= qi) && (kj <= qi + Wn);
                float s_ = NEG_BIG;
                if (valid) {
                    const float* kr = &smem_pool[(kj - c * 64) * 64];
                    float dot = 0.f;
#pragma unroll
                    for (int d = 0; d < 64; d += 4) {
                        float4 kv = *(const float4*)&kr[d];
                        dot += rq[d] * kv.x + rq[d+1] * kv.y
                             + rq[d+2] * kv.z + rq[d+3] * kv.w;
                    }
                    s_ = dot * 0.125f;
                }
                sc[j] = s_;
                mx = fmaxf(mx, s_);
            }
            float newm = fmaxf(m, mx);
            if (newm > NEG_BIG) {
                if (newm > m) {
                    float f = __expf(m - newm);
                    l *= f;
#pragma unroll
                    for (int d = 0; d < 64; ++d) acc[d] *= f;
                    m = newm;
                }
#pragma unroll
                for (int j = 0; j < 16; ++j) {
                    if (sc[j] > NEG_BIG) {
                        float p = __expf(sc[j] - m);
                        l += p;
                        const float* vr = &smem_pool[4096 + (kj0 + j - c * 64) * 64];
#pragma unroll
                        for (int d = 0; d < 64; d += 4) {
                            float4 vv = *(const float4*)&vr[d];
                            acc[d]   += p * vv.x; acc[d+1] += p * vv.y;
                            acc[d+2] += p * vv.z; acc[d+3] += p * vv.w;
                        }
                    }
                }
            }
        }
    }

    __syncthreads();
    float invl = 1.f / l;
#pragma unroll
    for (int d = 0; d < 64; ++d) smem_pool[qi * 64 + d] = acc[d] * invl;
    __syncthreads();

    float* obase = g_ctx + ((long)b * Sn + (long)n * Wn) * HIDn + h * HDn;
    for (int i = tid; i < 2048; i += 128) {
        int r  = i >> 4;
        int dq = i & 15;
        ((float4*)(obase + (long)r * HIDn))[dq] = ((const float4*)smem_pool)[i];
    }
}

// ---------------- launch (V GEMM at slot 4 for ncu capture) ------------------
extern "C" void kernel_launch(void* const* d_in, const int* in_sizes, int n_in,
                              void* d_out, int out_size)
{
    const float* X  = (const float*)d_in[0];
    const float* Wq = (const float*)d_in[1];
    const float* bq = (const float*)d_in[2];
    const float* Wk = (const float*)d_in[3];
    const float* bk = (const float*)d_in[4];
    const float* Wv = (const float*)d_in[5];
    const float* bv = (const float*)d_in[6];
    const float* Wo = (const float*)d_in[7];
    const float* bo = (const float*)d_in[8];
    float* out = (float*)d_out;

    dim3 gg(HIDn / BN, Mn / BM);   // (8, 64)
    gemm_mma<<<gg, 256>>>(X, Wq, bq, nullptr, 0);   // 1: Q (bf16 3-term)
    gemm_mma<<<gg, 256>>>(X, Wk, bk, nullptr, 1);   // 2: K (bf16 3-term)

    rope_kernel<<<(Bn * NHn * Sn * 32) / 256, 256>>>();  // 3: rope

    gemm_f16<<<gg, 256>>>(X, Wv, bv, nullptr, 2);   // 4: V (fp16 2-term) <- ncu

    dim3 ag(NBLK, NHn, Bn);
    attn_kernel<<<ag, 128>>>();                     // 5: attention

    gemm_f16<<<gg, 256>>>(nullptr, Wo, bo, out, 3); // 6: O (fp16 2-term)
}